// round 14
// baseline (speedup 1.0000x reference)
#include <cuda_runtime.h>
#include <cuda_fp16.h>
#include <math.h>
#include <stdint.h>

#define BATCH 2
#define NTOK 2048
#define TOK (BATCH*NTOK)
#define DIM 512
#define QKVN (3*DIM)
#define NHEADS 8
#define HDIM 64
#define KNN 32
#define PDIM 16
#define HID 2048
#define LN_EPS 1e-6f

// ---------------- scratch (device globals, no allocation) ----------------
__device__ __half g_qkvh[TOK*QKVN];
__device__ float  g_x1[TOK*DIM];
__device__ __half g_xnormh[TOK*DIM];
__device__ __half g_attnh[TOK*DIM];
__device__ __half g_x2nh[TOK*DIM];
__device__ __half g_hidh[TOK*HID];
__device__ __half g_WqkvT[QKVN*DIM];
__device__ __half g_WoT[DIM*DIM];
__device__ __half g_W1T[DIM*HID];
__device__ __half g_W2T[HID*DIM];
__device__ float  g_bqkv[QKVN];
__device__ int    g_tidx[TOK*KNN];
__device__ float  g_tdist[TOK*KNN];
__device__ float  g_cx[TOK];

__device__ __forceinline__ uint32_t smem_u32(const void* p) {
    uint32_t a;
    asm("{ .reg .u64 t; cvta.to.shared.u64 t, %1; cvt.u32.u64 %0, t; }" : "=r"(a) : "l"(p));
    return a;
}
__device__ __forceinline__ float fast_tanh(float x) {
    float t = __expf(2.0f*x);
    return (t - 1.0f) / (t + 1.0f);
}
__device__ __forceinline__ float gelu_f(float x) {
    float x3 = x*x*x;
    return 0.5f*x*(1.0f + fast_tanh(0.7978845608028654f*(x + 0.044715f*x3)));
}

// ---------------- prep: flat-grid weight transposes + cx + bias pack ----------------
__global__ __launch_bounds__(256)
void prep_kernel(const float* __restrict__ Wq, const float* __restrict__ Wk,
                 const float* __restrict__ Wv, const float* __restrict__ Wo,
                 const float* __restrict__ W1, const float* __restrict__ W2,
                 const float* __restrict__ bq, const float* __restrict__ bk,
                 const float* __restrict__ bv, const float* __restrict__ pos,
                 const float* __restrict__ cptr) {
    int bid = blockIdx.x;
    if (bid >= 3072) {
        int bx = bid - 3072;
        if (bx < 16) {
            int i = bx*256 + threadIdx.x;
            const float* p = pos + (size_t)i*PDIM;
            float s = 0.f;
            #pragma unroll
            for (int t = 0; t < PDIM; t += 4) {
                float4 v = *(const float4*)(p + t);
                s += v.x*v.x + v.y*v.y + v.z*v.z + v.w*v.w;
            }
            g_cx[i] = 1.f - (*cptr)*s;
        } else {
            for (int i = threadIdx.x; i < DIM; i += 256) {
                g_bqkv[i]         = bq[i];
                g_bqkv[DIM + i]   = bk[i];
                g_bqkv[2*DIM + i] = bv[i];
            }
        }
        return;
    }
    const float* W; __half* Wt; int Kk, Nn, idx, nnb;
    if (bid < 1024) {
        int which = bid >> 8;
        idx = bid & 255; nnb = 16; Kk = DIM; Nn = DIM;
        if      (which == 0) { W = Wq; Wt = g_WqkvT; }
        else if (which == 1) { W = Wk; Wt = g_WqkvT + DIM*DIM; }
        else if (which == 2) { W = Wv; Wt = g_WqkvT + 2*DIM*DIM; }
        else                 { W = Wo; Wt = g_WoT; }
    } else if (bid < 2048) {
        idx = bid - 1024; nnb = 64; Kk = DIM; Nn = HID; W = W1; Wt = g_W1T;
    } else {
        idx = bid - 2048; nnb = 16; Kk = HID; Nn = DIM; W = W2; Wt = g_W2T;
    }
    int nb = (idx % nnb)*32, kb = (idx / nnb)*32;
    __shared__ float t[32][33];
    int tx = threadIdx.x & 31, ty = (threadIdx.x >> 5) * 4;
    #pragma unroll
    for (int i = 0; i < 4; i++)
        t[ty+i][tx] = W[(size_t)(kb+ty+i)*Nn + nb+tx];
    __syncthreads();
    #pragma unroll
    for (int i = 0; i < 4; i++)
        Wt[(size_t)(nb+ty+i)*Kk + kb+tx] = __float2half(t[tx][ty+i]);
}

// ---------------- LayerNorm -> fp16 ----------------
__global__ __launch_bounds__(256)
void ln_kernel(const float* __restrict__ xin, const float* __restrict__ sc,
               const float* __restrict__ bi, __half* __restrict__ outp) {
    __shared__ float red[8];
    int row = blockIdx.x;
    const float* xr = xin + (size_t)row*DIM;
    int t = threadIdx.x, lane = t & 31, wid = t >> 5;
    float v0 = xr[t], v1 = xr[t+256];
    float s = v0 + v1;
    #pragma unroll
    for (int o = 16; o; o >>= 1) s += __shfl_xor_sync(0xffffffffu, s, o);
    if (lane == 0) red[wid] = s;
    __syncthreads();
    float tot = red[0]+red[1]+red[2]+red[3]+red[4]+red[5]+red[6]+red[7];
    float m = tot * (1.0f/DIM);
    float d0 = v0 - m, d1 = v1 - m;
    float ss = d0*d0 + d1*d1;
    __syncthreads();
    #pragma unroll
    for (int o = 16; o; o >>= 1) ss += __shfl_xor_sync(0xffffffffu, ss, o);
    if (lane == 0) red[wid] = ss;
    __syncthreads();
    float var = (red[0]+red[1]+red[2]+red[3]+red[4]+red[5]+red[6]+red[7]) * (1.0f/DIM);
    float r = rsqrtf(var + LN_EPS);
    outp[(size_t)row*DIM + t]     = __float2half(d0*r*sc[t]     + bi[t]);
    outp[(size_t)row*DIM + t+256] = __float2half(d1*r*sc[t+256] + bi[t+256]);
}

// ---------------- HMMA fp16 GEMM: 3-stage, BKC=32, templated TM ----------------
#define TN 128
#define BKC 32
#define SPITCH 40
#define NSTAGE 3

// EPI: 0=+bias->f32  1=+bias+Res->f32  2=gelu(+bias)->f16  3=+bias->f16
template<int EPI, int TMp>
__global__ __launch_bounds__(256)
void hgemm_mma(const __half* __restrict__ A, const __half* __restrict__ Bt,
               const float* __restrict__ bias, const float* __restrict__ Res,
               void* __restrict__ Cout, int Nn, int Kk) {
    extern __shared__ __align__(16) char dsm[];
    constexpr int MI = TMp / 32;
    const uint32_t base = smem_u32(dsm);
    const uint32_t aSz = TMp*SPITCH*2;
    const uint32_t bSz = TN*SPITCH*2;

    const int tid = threadIdx.x;
    const int lane = tid & 31, wid = tid >> 5;
    const int bm = blockIdx.y * TMp, bn = blockIdx.x * TN;
    const int wm = (wid >> 2) * (TMp/2);
    const int wn = (wid & 3) * 32;

    float acc[MI][4][4];
    #pragma unroll
    for (int i = 0; i < MI; i++)
        #pragma unroll
        for (int j = 0; j < 4; j++)
            #pragma unroll
            for (int r = 0; r < 4; r++) acc[i][j][r] = 0.f;

    const int nch = Kk / BKC;
    const int b_lr = tid >> 1, b_lc = (tid & 1) * 2;
    const int a_lr128 = tid >> 1, a_lc128 = (tid & 1) * 2;
    const int a_lr64  = tid >> 2, a_lc64  = tid & 3;

    #define LOAD_TILE(k0, st) do { \
        if (TMp == 128) { \
            const __half* ga = A + (size_t)(bm+a_lr128)*Kk + (k0) + a_lc128*8; \
            uint32_t da = base + (st)*aSz + (a_lr128*SPITCH + a_lc128*8)*2; \
            asm volatile("cp.async.cg.shared.global [%0], [%1], 16;" :: "r"(da), "l"(ga)); \
            asm volatile("cp.async.cg.shared.global [%0], [%1], 16;" :: "r"(da+16), "l"(ga+8)); \
        } else { \
            const __half* ga = A + (size_t)(bm+a_lr64)*Kk + (k0) + a_lc64*8; \
            uint32_t da = base + (st)*aSz + (a_lr64*SPITCH + a_lc64*8)*2; \
            asm volatile("cp.async.cg.shared.global [%0], [%1], 16;" :: "r"(da), "l"(ga)); \
        } \
        const __half* gb = Bt + (size_t)(bn+b_lr)*Kk + (k0) + b_lc*8; \
        uint32_t db = base + NSTAGE*aSz + (st)*bSz + (b_lr*SPITCH + b_lc*8)*2; \
        asm volatile("cp.async.cg.shared.global [%0], [%1], 16;" :: "r"(db), "l"(gb)); \
        asm volatile("cp.async.cg.shared.global [%0], [%1], 16;" :: "r"(db+16), "l"(gb+8)); \
        asm volatile("cp.async.commit_group;"); \
    } while (0)

    LOAD_TILE(0, 0);
    LOAD_TILE(BKC, 1);

    const int a_row = wm + (lane & 15);
    const int a_c8  = (lane >> 4) * 8;
    const int b_row0 = wn + (lane & 7) + (lane >> 4) * 8;
    const int b_c8   = ((lane >> 3) & 1) * 8;

    for (int ch = 0; ch < nch; ch++) {
        int st = ch % NSTAGE;
        if (ch + 1 < nch) asm volatile("cp.async.wait_group 1;");
        else              asm volatile("cp.async.wait_group 0;");
        __syncthreads();
        if (ch + 2 < nch) LOAD_TILE((ch+2)*BKC, (ch+2) % NSTAGE);

        const uint32_t aBase = base + st*aSz;
        const uint32_t bBase = base + NSTAGE*aSz + st*bSz;
        #pragma unroll
        for (int ks = 0; ks < 2; ks++) {
            uint32_t a[MI][4];
            #pragma unroll
            for (int mi = 0; mi < MI; mi++) {
                uint32_t ad = aBase + ((a_row + mi*16)*SPITCH + ks*16 + a_c8)*2;
                asm volatile("ldmatrix.sync.aligned.m8n8.x4.shared.b16 {%0,%1,%2,%3}, [%4];"
                    : "=r"(a[mi][0]),"=r"(a[mi][1]),"=r"(a[mi][2]),"=r"(a[mi][3]) : "r"(ad));
            }
            uint32_t b[2][4];
            #pragma unroll
            for (int pi = 0; pi < 2; pi++) {
                uint32_t bd = bBase + ((b_row0 + pi*16)*SPITCH + ks*16 + b_c8)*2;
                asm volatile("ldmatrix.sync.aligned.m8n8.x4.shared.b16 {%0,%1,%2,%3}, [%4];"
                    : "=r"(b[pi][0]),"=r"(b[pi][1]),"=r"(b[pi][2]),"=r"(b[pi][3]) : "r"(bd));
            }
            #pragma unroll
            for (int mi = 0; mi < MI; mi++)
                #pragma unroll
                for (int ni = 0; ni < 4; ni++) {
                    uint32_t b0 = b[ni>>1][(ni&1)*2];
                    uint32_t b1 = b[ni>>1][(ni&1)*2+1];
                    asm volatile(
                        "mma.sync.aligned.m16n8k16.row.col.f32.f16.f16.f32 "
                        "{%0,%1,%2,%3}, {%4,%5,%6,%7}, {%8,%9}, {%0,%1,%2,%3};"
                        : "+f"(acc[mi][ni][0]), "+f"(acc[mi][ni][1]),
                          "+f"(acc[mi][ni][2]), "+f"(acc[mi][ni][3])
                        : "r"(a[mi][0]), "r"(a[mi][1]), "r"(a[mi][2]), "r"(a[mi][3]),
                          "r"(b0), "r"(b1));
                }
        }
    }
    #undef LOAD_TILE
    __syncthreads();

    #pragma unroll
    for (int mi = 0; mi < MI; mi++) {
        #pragma unroll
        for (int ni = 0; ni < 4; ni++) {
            int r0 = bm + wm + mi*16 + (lane >> 2);
            int c0 = bn + wn + ni*8 + (lane & 3)*2;
            float bv0 = bias[c0], bv1 = bias[c0+1];
            float v0 = acc[mi][ni][0] + bv0;
            float v1 = acc[mi][ni][1] + bv1;
            float v2 = acc[mi][ni][2] + bv0;
            float v3 = acc[mi][ni][3] + bv1;
            if (EPI == 1) {
                const float* rp0 = Res + (size_t)r0*Nn + c0;
                const float* rp1 = Res + (size_t)(r0+8)*Nn + c0;
                v0 += rp0[0]; v1 += rp0[1];
                v2 += rp1[0]; v3 += rp1[1];
            }
            if (EPI == 2) {
                __half* cp = (__half*)Cout;
                *(__half2*)(cp + (size_t)r0*Nn + c0)     = __floats2half2_rn(gelu_f(v0), gelu_f(v1));
                *(__half2*)(cp + (size_t)(r0+8)*Nn + c0) = __floats2half2_rn(gelu_f(v2), gelu_f(v3));
            } else if (EPI == 3) {
                __half* cp = (__half*)Cout;
                *(__half2*)(cp + (size_t)r0*Nn + c0)     = __floats2half2_rn(v0, v1);
                *(__half2*)(cp + (size_t)(r0+8)*Nn + c0) = __floats2half2_rn(v2, v3);
            } else {
                float* cp = (float*)Cout;
                *(float2*)(cp + (size_t)r0*Nn + c0)     = make_float2(v0, v1);
                *(float2*)(cp + (size_t)(r0+8)*Nn + c0) = make_float2(v2, v3);
            }
        }
    }
}

// ---------------- fused distance + register-resident top-K ----------------
// One block per query row; surrogates computed in registers, no 32MB intermediate.
__global__ __launch_bounds__(256)
void topk_kernel(const float* __restrict__ pos, const float* __restrict__ cptr) {
    __shared__ float spi[PDIM];
    __shared__ float sval[8][32];
    __shared__ int   sjdx[8][32];
    int row = blockIdx.x;
    int b = row / NTOK;
    int tid = threadIdx.x, lane = tid & 31, w = tid >> 5;

    if (tid < PDIM) spi[tid] = pos[(size_t)row*PDIM + tid];
    __syncthreads();
    float c = *cptr;
    float cxi = g_cx[row];
    const float* pb = pos + (size_t)b*NTOK*PDIM;
    const float* cxb = g_cx + (size_t)b*NTOK;

    float rv[8];
    #pragma unroll
    for (int it = 0; it < 8; it++) {
        int j = it*256 + tid;
        const float* pj = pb + (size_t)j*PDIM;
        float d2 = 0.f;
        #pragma unroll
        for (int t4 = 0; t4 < PDIM; t4 += 4) {
            float4 v = *(const float4*)(pj + t4);
            float e0 = spi[t4+0] - v.x;
            float e1 = spi[t4+1] - v.y;
            float e2 = spi[t4+2] - v.z;
            float e3 = spi[t4+3] - v.w;
            d2 = fmaf(e0, e0, d2); d2 = fmaf(e1, e1, d2);
            d2 = fmaf(e2, e2, d2); d2 = fmaf(e3, e3, d2);
        }
        float den = fmaxf(cxi * cxb[j], 1e-8f);
        rv[it] = d2 / den;
    }

    // phase 1: per-warp top-32
    #pragma unroll 1
    for (int k = 0; k < KNN; k++) {
        float bv = rv[0]; int bs = 0;
        #pragma unroll
        for (int i = 1; i < 8; i++) if (rv[i] < bv) { bv = rv[i]; bs = i; }
        int bj = bs*256 + tid;
        #pragma unroll
        for (int o = 16; o; o >>= 1) {
            float ov = __shfl_xor_sync(0xffffffffu, bv, o);
            int   oj = __shfl_xor_sync(0xffffffffu, bj, o);
            if (ov < bv || (ov == bv && oj < bj)) { bv = ov; bj = oj; }
        }
        if ((bj & 255) == tid) {
            int slot = bj >> 8;
            #pragma unroll
            for (int i = 0; i < 8; i++) if (i == slot) rv[i] = 3.4e38f;
        }
        if (lane == k) { sval[w][k] = bv; sjdx[w][k] = bj; }
    }
    __syncthreads();

    // phase 2: warp 0 merges 8x32 candidates
    if (w == 0) {
        float mv[8]; int mj[8];
        #pragma unroll
        for (int i = 0; i < 8; i++) { mv[i] = sval[i][lane]; mj[i] = sjdx[i][lane]; }
        float isc = rsqrtf(c);
        #pragma unroll 1
        for (int k = 0; k < KNN; k++) {
            float bv = mv[0]; int bs = 0; int bjv = mj[0];
            #pragma unroll
            for (int i = 1; i < 8; i++)
                if (mv[i] < bv || (mv[i] == bv && mj[i] < bjv)) { bv = mv[i]; bs = i; bjv = mj[i]; }
            int bj = bjv;
            int bc = bs*32 + lane;
            #pragma unroll
            for (int o = 16; o; o >>= 1) {
                float ov = __shfl_xor_sync(0xffffffffu, bv, o);
                int   oj = __shfl_xor_sync(0xffffffffu, bj, o);
                int   oc = __shfl_xor_sync(0xffffffffu, bc, o);
                if (ov < bv || (ov == bv && oj < bj)) { bv = ov; bj = oj; bc = oc; }
            }
            if (lane == (bc & 31)) {
                int slot = bc >> 5;
                #pragma unroll
                for (int i = 0; i < 8; i++) if (i == slot) mv[i] = 3.4e38f;
            }
            if (lane == k) {
                g_tidx[row*KNN + k] = bj;
                float arg = fmaxf(fmaf(2.f*c, bv, 1.f), 1.f + 1e-7f);
                g_tdist[row*KNN + k] = acoshf(arg) * isc;
            }
        }
    }
}

// ---------------- kNN attention: K staged via smem (coalesced gather) ----------------
#define KPITCH 257

__global__ __launch_bounds__(256)
void attn_kernel(const float* __restrict__ ltau, const float* __restrict__ ascl) {
    __shared__ uint32_t sk[KNN*KPITCH];
    __shared__ int   sidx[KNN];
    __shared__ float sdist[KNN];
    __shared__ float sw[NHEADS][KNN];
    int row = blockIdx.x;
    int b = row / NTOK;
    int t = threadIdx.x;
    int h = t >> 5, lane = t & 31;
    if (t < KNN) { sidx[t] = g_tidx[row*KNN + t]; sdist[t] = g_tdist[row*KNN + t]; }
    __syncthreads();

    #pragma unroll
    for (int rr = 0; rr < 4; rr++) {
        int j = h*4 + rr;
        const uint32_t* src = (const uint32_t*)(g_qkvh + (size_t)(b*NTOK + sidx[j])*QKVN + DIM);
        uint32_t* dst = &sk[j*KPITCH];
        #pragma unroll
        for (int it = 0; it < 8; it++)
            dst[it*32 + lane] = src[it*32 + lane];
    }
    __syncthreads();

    float inv_tau = 1.0f / fmaxf(__expf(ltau[0]), 1e-8f);
    float as = ascl[0];

    const __half* qrow = g_qkvh + (size_t)row*QKVN + h*HDIM;
    const uint32_t* krow = &sk[lane*KPITCH + h*32];
    float dot = 0.f;
    #pragma unroll
    for (int d8 = 0; d8 < 8; d8++) {
        float4 qb = *(const float4*)(qrow + d8*8);
        const __half2* q2 = (const __half2*)&qb;
        #pragma unroll
        for (int p = 0; p < 4; p++) {
            uint32_t kw = krow[d8*4 + p];
            float2 ka = __half22float2(*(const __half2*)&kw);
            float2 qa = __half22float2(q2[p]);
            dot = fmaf(qa.x, ka.x, dot);
            dot = fmaf(qa.y, ka.y, dot);
        }
    }
    float sc = as * fast_tanh(dot*0.125f - sdist[lane]*inv_tau);
    float mx = sc;
    #pragma unroll
    for (int o = 16; o; o >>= 1) mx = fmaxf(mx, __shfl_xor_sync(0xffffffffu, mx, o));
    float e = __expf(sc - mx);
    float sum = e;
    #pragma unroll
    for (int o = 16; o; o >>= 1) sum += __shfl_xor_sync(0xffffffffu, sum, o);
    sw[h][lane] = e / sum;
    __syncwarp();

    float o0 = 0.f, o1 = 0.f;
    #pragma unroll 8
    for (int j = 0; j < KNN; j++) {
        const __half* vrow = g_qkvh + (size_t)(b*NTOK + sidx[j])*QKVN + 2*DIM + h*HDIM;
        float2 vv = __half22float2(*(const __half2*)(vrow + lane*2));
        float wj = sw[h][j];
        o0 = fmaf(wj, vv.x, o0);
        o1 = fmaf(wj, vv.y, o1);
    }
    *(__half2*)(g_attnh + (size_t)row*DIM + h*HDIM + lane*2) = __floats2half2_rn(o0, o1);
}

// ---------------- launch ----------------
extern "C" void kernel_launch(void* const* d_in, const int* in_sizes, int n_in,
                              void* d_out, int out_size) {
    const float* x    = (const float*)d_in[0];
    const float* pos  = (const float*)d_in[1];
    const float* c    = (const float*)d_in[2];
    const float* Wq   = (const float*)d_in[3];
    const float* bq   = (const float*)d_in[4];
    const float* Wk   = (const float*)d_in[5];
    const float* bk   = (const float*)d_in[6];
    const float* Wv   = (const float*)d_in[7];
    const float* bv   = (const float*)d_in[8];
    const float* Wo   = (const float*)d_in[9];
    const float* bo   = (const float*)d_in[10];
    const float* W1   = (const float*)d_in[11];
    const float* b1   = (const float*)d_in[12];
    const float* W2   = (const float*)d_in[13];
    const float* b2   = (const float*)d_in[14];
    const float* ln1s = (const float*)d_in[15];
    const float* ln1b = (const float*)d_in[16];
    const float* ln2s = (const float*)d_in[17];
    const float* ln2b = (const float*)d_in[18];
    const float* ltau = (const float*)d_in[19];
    const float* ascl = (const float*)d_in[20];
    float* out = (float*)d_out;

    float *x1, *bqkv;
    __half *qkvh, *xnh, *ath, *x2h, *hih, *WqkvT, *WoT, *W1T, *W2T;
    cudaGetSymbolAddress((void**)&qkvh, g_qkvh);
    cudaGetSymbolAddress((void**)&x1,   g_x1);
    cudaGetSymbolAddress((void**)&bqkv, g_bqkv);
    cudaGetSymbolAddress((void**)&xnh,  g_xnormh);
    cudaGetSymbolAddress((void**)&ath,  g_attnh);
    cudaGetSymbolAddress((void**)&x2h,  g_x2nh);
    cudaGetSymbolAddress((void**)&hih,  g_hidh);
    cudaGetSymbolAddress((void**)&WqkvT, g_WqkvT);
    cudaGetSymbolAddress((void**)&WoT,  g_WoT);
    cudaGetSymbolAddress((void**)&W1T,  g_W1T);
    cudaGetSymbolAddress((void**)&W2T,  g_W2T);

    const int smem128 = NSTAGE * (128 + TN) * SPITCH * 2;   // 61,440 B
    const int smem64  = NSTAGE * (64  + TN) * SPITCH * 2;   // 46,080 B
    cudaFuncSetAttribute(hgemm_mma<3,128>, cudaFuncAttributeMaxDynamicSharedMemorySize, smem128);
    cudaFuncSetAttribute(hgemm_mma<2,128>, cudaFuncAttributeMaxDynamicSharedMemorySize, smem128);
    cudaFuncSetAttribute(hgemm_mma<1,64>,  cudaFuncAttributeMaxDynamicSharedMemorySize, smem64);

    dim3 gqkv(QKVN/TN, TOK/128);   // (12, 32)
    dim3 g512(DIM/TN,  TOK/64);    // (4, 64) for TM=64
    dim3 gh  (HID/TN,  TOK/128);   // (16, 32)

    prep_kernel<<<3089, 256>>>(Wq, Wk, Wv, Wo, W1, W2, bq, bk, bv, pos, c);
    ln_kernel<<<TOK, 256>>>(x, ln1s, ln1b, xnh);
    hgemm_mma<3,128><<<gqkv, 256, smem128>>>(xnh, WqkvT, bqkv, nullptr, qkvh, QKVN, DIM);
    topk_kernel<<<TOK, 256>>>(pos, c);
    attn_kernel<<<TOK, 256>>>(ltau, ascl);
    hgemm_mma<1,64><<<g512, 256, smem64>>>(ath, WoT, bo, x, x1, DIM, DIM);
    ln_kernel<<<TOK, 256>>>(x1, ln2s, ln2b, x2h);
    hgemm_mma<2,128><<<gh, 256, smem128>>>(x2h, W1T, b1, nullptr, hih, HID, DIM);
    hgemm_mma<1,64><<<g512, 256, smem64>>>(hih, W2T, b2, x1, out, DIM, HID);
}

// round 15
// speedup vs baseline: 1.1072x; 1.1072x over previous
#include <cuda_runtime.h>
#include <cuda_fp16.h>
#include <math.h>
#include <stdint.h>

#define BATCH 2
#define NTOK 2048
#define TOK (BATCH*NTOK)
#define DIM 512
#define QKVN (3*DIM)
#define NHEADS 8
#define HDIM 64
#define KNN 32
#define PDIM 16
#define HID 2048
#define LN_EPS 1e-6f
#define RB 128

// ---------------- scratch (device globals, no allocation) ----------------
__device__ __half g_qkvh[TOK*QKVN];
__device__ float  g_x1[TOK*DIM];
__device__ __half g_xnormh[TOK*DIM];
__device__ __half g_attnh[TOK*DIM];
__device__ __half g_x2nh[TOK*DIM];
__device__ __half g_hidh[TOK*HID];
__device__ __half g_WqkvT[QKVN*DIM];
__device__ __half g_WoT[DIM*DIM];
__device__ __half g_W1T[DIM*HID];
__device__ __half g_W2T[HID*DIM];
__device__ float  g_bqkv[QKVN];
__device__ int    g_tidx[TOK*KNN];
__device__ float  g_tdist[TOK*KNN];
__device__ float  g_pnsq[TOK];
__device__ float  g_cx[TOK];
__device__ float  g_rmat[(size_t)BATCH*NTOK*NTOK];

__device__ __forceinline__ uint32_t smem_u32(const void* p) {
    uint32_t a;
    asm("{ .reg .u64 t; cvta.to.shared.u64 t, %1; cvt.u32.u64 %0, t; }" : "=r"(a) : "l"(p));
    return a;
}
__device__ __forceinline__ float fast_tanh(float x) {
    float t = __expf(2.0f*x);
    return (t - 1.0f) / (t + 1.0f);
}
__device__ __forceinline__ float gelu_f(float x) {
    float x3 = x*x*x;
    return 0.5f*x*(1.0f + fast_tanh(0.7978845608028654f*(x + 0.044715f*x3)));
}

// ---------------- prep: flat-grid weight transposes + pnsq/cx + bias pack ----------------
__global__ __launch_bounds__(256)
void prep_kernel(const float* __restrict__ Wq, const float* __restrict__ Wk,
                 const float* __restrict__ Wv, const float* __restrict__ Wo,
                 const float* __restrict__ W1, const float* __restrict__ W2,
                 const float* __restrict__ bq, const float* __restrict__ bk,
                 const float* __restrict__ bv, const float* __restrict__ pos,
                 const float* __restrict__ cptr) {
    int bid = blockIdx.x;
    if (bid >= 3072) {
        int bx = bid - 3072;
        if (bx < 16) {
            int i = bx*256 + threadIdx.x;
            const float* p = pos + (size_t)i*PDIM;
            float s = 0.f;
            #pragma unroll
            for (int t = 0; t < PDIM; t += 4) {
                float4 v = *(const float4*)(p + t);
                s += v.x*v.x + v.y*v.y + v.z*v.z + v.w*v.w;
            }
            float c = *cptr;
            g_pnsq[i] = s;
            g_cx[i]   = 1.f - c*s;
        } else {
            for (int i = threadIdx.x; i < DIM; i += 256) {
                g_bqkv[i]         = bq[i];
                g_bqkv[DIM + i]   = bk[i];
                g_bqkv[2*DIM + i] = bv[i];
            }
        }
        return;
    }
    const float* W; __half* Wt; int Kk, Nn, idx, nnb;
    if (bid < 1024) {
        int which = bid >> 8;
        idx = bid & 255; nnb = 16; Kk = DIM; Nn = DIM;
        if      (which == 0) { W = Wq; Wt = g_WqkvT; }
        else if (which == 1) { W = Wk; Wt = g_WqkvT + DIM*DIM; }
        else if (which == 2) { W = Wv; Wt = g_WqkvT + 2*DIM*DIM; }
        else                 { W = Wo; Wt = g_WoT; }
    } else if (bid < 2048) {
        idx = bid - 1024; nnb = 64; Kk = DIM; Nn = HID; W = W1; Wt = g_W1T;
    } else {
        idx = bid - 2048; nnb = 16; Kk = HID; Nn = DIM; W = W2; Wt = g_W2T;
    }
    int nb = (idx % nnb)*32, kb = (idx / nnb)*32;
    __shared__ float t[32][33];
    int tx = threadIdx.x & 31, ty = (threadIdx.x >> 5) * 4;
    #pragma unroll
    for (int i = 0; i < 4; i++)
        t[ty+i][tx] = W[(size_t)(kb+ty+i)*Nn + nb+tx];
    __syncthreads();
    #pragma unroll
    for (int i = 0; i < 4; i++)
        Wt[(size_t)(nb+ty+i)*Kk + kb+tx] = __float2half(t[tx][ty+i]);
}

// ---------------- LayerNorm -> fp16 ----------------
__global__ __launch_bounds__(256)
void ln_kernel(const float* __restrict__ xin, const float* __restrict__ sc,
               const float* __restrict__ bi, __half* __restrict__ outp) {
    __shared__ float red[8];
    int row = blockIdx.x;
    const float* xr = xin + (size_t)row*DIM;
    int t = threadIdx.x, lane = t & 31, wid = t >> 5;
    float v0 = xr[t], v1 = xr[t+256];
    float s = v0 + v1;
    #pragma unroll
    for (int o = 16; o; o >>= 1) s += __shfl_xor_sync(0xffffffffu, s, o);
    if (lane == 0) red[wid] = s;
    __syncthreads();
    float tot = red[0]+red[1]+red[2]+red[3]+red[4]+red[5]+red[6]+red[7];
    float m = tot * (1.0f/DIM);
    float d0 = v0 - m, d1 = v1 - m;
    float ss = d0*d0 + d1*d1;
    __syncthreads();
    #pragma unroll
    for (int o = 16; o; o >>= 1) ss += __shfl_xor_sync(0xffffffffu, ss, o);
    if (lane == 0) red[wid] = ss;
    __syncthreads();
    float var = (red[0]+red[1]+red[2]+red[3]+red[4]+red[5]+red[6]+red[7]) * (1.0f/DIM);
    float r = rsqrtf(var + LN_EPS);
    outp[(size_t)row*DIM + t]     = __float2half(d0*r*sc[t]     + bi[t]);
    outp[(size_t)row*DIM + t+256] = __float2half(d1*r*sc[t+256] + bi[t+256]);
}

// ---------------- HMMA fp16 GEMM: 3-stage, BKC=32, templated TM ----------------
#define TN 128
#define BKC 32
#define SPITCH 40   // 32 data + 8 pad halves; 80B row stride -> ldmatrix conflict-free
#define NSTAGE 3

// EPI: 0=+bias->f32  1=+bias+Res->f32  2=gelu(+bias)->f16  3=+bias->f16
template<int EPI, int TMp>
__global__ __launch_bounds__(256)
void hgemm_mma(const __half* __restrict__ A, const __half* __restrict__ Bt,
               const float* __restrict__ bias, const float* __restrict__ Res,
               void* __restrict__ Cout, int Nn, int Kk) {
    extern __shared__ __align__(16) char dsm[];
    constexpr int MI = TMp / 32;            // m-frags per warp (4 at TM=128, 2 at TM=64)
    const uint32_t base = smem_u32(dsm);
    const uint32_t aSz = TMp*SPITCH*2;
    const uint32_t bSz = TN*SPITCH*2;

    const int tid = threadIdx.x;
    const int lane = tid & 31, wid = tid >> 5;
    const int bm = blockIdx.y * TMp, bn = blockIdx.x * TN;
    const int wm = (wid >> 2) * (TMp/2);
    const int wn = (wid & 3) * 32;

    float acc[MI][4][4];
    #pragma unroll
    for (int i = 0; i < MI; i++)
        #pragma unroll
        for (int j = 0; j < 4; j++)
            #pragma unroll
            for (int r = 0; r < 4; r++) acc[i][j][r] = 0.f;

    const int nch = Kk / BKC;
    // B loader: 128 rows, 2 vec16/thread.  A loader: TMp rows.
    const int b_lr = tid >> 1, b_lc = (tid & 1) * 2;
    const int a_lr128 = tid >> 1, a_lc128 = (tid & 1) * 2;
    const int a_lr64  = tid >> 2, a_lc64  = tid & 3;

    #define LOAD_TILE(k0, st) do { \
        if (TMp == 128) { \
            const __half* ga = A + (size_t)(bm+a_lr128)*Kk + (k0) + a_lc128*8; \
            uint32_t da = base + (st)*aSz + (a_lr128*SPITCH + a_lc128*8)*2; \
            asm volatile("cp.async.cg.shared.global [%0], [%1], 16;" :: "r"(da), "l"(ga)); \
            asm volatile("cp.async.cg.shared.global [%0], [%1], 16;" :: "r"(da+16), "l"(ga+8)); \
        } else { \
            const __half* ga = A + (size_t)(bm+a_lr64)*Kk + (k0) + a_lc64*8; \
            uint32_t da = base + (st)*aSz + (a_lr64*SPITCH + a_lc64*8)*2; \
            asm volatile("cp.async.cg.shared.global [%0], [%1], 16;" :: "r"(da), "l"(ga)); \
        } \
        const __half* gb = Bt + (size_t)(bn+b_lr)*Kk + (k0) + b_lc*8; \
        uint32_t db = base + NSTAGE*aSz + (st)*bSz + (b_lr*SPITCH + b_lc*8)*2; \
        asm volatile("cp.async.cg.shared.global [%0], [%1], 16;" :: "r"(db), "l"(gb)); \
        asm volatile("cp.async.cg.shared.global [%0], [%1], 16;" :: "r"(db+16), "l"(gb+8)); \
        asm volatile("cp.async.commit_group;"); \
    } while (0)

    LOAD_TILE(0, 0);
    LOAD_TILE(BKC, 1);

    const int a_row = wm + (lane & 15);
    const int a_c8  = (lane >> 4) * 8;
    const int b_row0 = wn + (lane & 7) + (lane >> 4) * 8;
    const int b_c8   = ((lane >> 3) & 1) * 8;

    for (int ch = 0; ch < nch; ch++) {
        int st = ch % NSTAGE;
        if (ch + 1 < nch) asm volatile("cp.async.wait_group 1;");
        else              asm volatile("cp.async.wait_group 0;");
        __syncthreads();
        if (ch + 2 < nch) LOAD_TILE((ch+2)*BKC, (ch+2) % NSTAGE);

        const uint32_t aBase = base + st*aSz;
        const uint32_t bBase = base + NSTAGE*aSz + st*bSz;
        #pragma unroll
        for (int ks = 0; ks < 2; ks++) {
            uint32_t a[MI][4];
            #pragma unroll
            for (int mi = 0; mi < MI; mi++) {
                uint32_t ad = aBase + ((a_row + mi*16)*SPITCH + ks*16 + a_c8)*2;
                asm volatile("ldmatrix.sync.aligned.m8n8.x4.shared.b16 {%0,%1,%2,%3}, [%4];"
                    : "=r"(a[mi][0]),"=r"(a[mi][1]),"=r"(a[mi][2]),"=r"(a[mi][3]) : "r"(ad));
            }
            uint32_t b[2][4];
            #pragma unroll
            for (int pi = 0; pi < 2; pi++) {
                uint32_t bd = bBase + ((b_row0 + pi*16)*SPITCH + ks*16 + b_c8)*2;
                asm volatile("ldmatrix.sync.aligned.m8n8.x4.shared.b16 {%0,%1,%2,%3}, [%4];"
                    : "=r"(b[pi][0]),"=r"(b[pi][1]),"=r"(b[pi][2]),"=r"(b[pi][3]) : "r"(bd));
            }
            #pragma unroll
            for (int mi = 0; mi < MI; mi++)
                #pragma unroll
                for (int ni = 0; ni < 4; ni++) {
                    uint32_t b0 = b[ni>>1][(ni&1)*2];
                    uint32_t b1 = b[ni>>1][(ni&1)*2+1];
                    asm volatile(
                        "mma.sync.aligned.m16n8k16.row.col.f32.f16.f16.f32 "
                        "{%0,%1,%2,%3}, {%4,%5,%6,%7}, {%8,%9}, {%0,%1,%2,%3};"
                        : "+f"(acc[mi][ni][0]), "+f"(acc[mi][ni][1]),
                          "+f"(acc[mi][ni][2]), "+f"(acc[mi][ni][3])
                        : "r"(a[mi][0]), "r"(a[mi][1]), "r"(a[mi][2]), "r"(a[mi][3]),
                          "r"(b0), "r"(b1));
                }
        }
    }
    #undef LOAD_TILE
    __syncthreads();

    #pragma unroll
    for (int mi = 0; mi < MI; mi++) {
        #pragma unroll
        for (int ni = 0; ni < 4; ni++) {
            int r0 = bm + wm + mi*16 + (lane >> 2);
            int c0 = bn + wn + ni*8 + (lane & 3)*2;
            float bv0 = bias[c0], bv1 = bias[c0+1];
            float v0 = acc[mi][ni][0] + bv0;
            float v1 = acc[mi][ni][1] + bv1;
            float v2 = acc[mi][ni][2] + bv0;
            float v3 = acc[mi][ni][3] + bv1;
            if (EPI == 1) {
                const float* rp0 = Res + (size_t)r0*Nn + c0;
                const float* rp1 = Res + (size_t)(r0+8)*Nn + c0;
                v0 += rp0[0]; v1 += rp0[1];
                v2 += rp1[0]; v3 += rp1[1];
            }
            if (EPI == 2) {
                __half* cp = (__half*)Cout;
                *(__half2*)(cp + (size_t)r0*Nn + c0)     = __floats2half2_rn(gelu_f(v0), gelu_f(v1));
                *(__half2*)(cp + (size_t)(r0+8)*Nn + c0) = __floats2half2_rn(gelu_f(v2), gelu_f(v3));
            } else if (EPI == 3) {
                __half* cp = (__half*)Cout;
                *(__half2*)(cp + (size_t)r0*Nn + c0)     = __floats2half2_rn(v0, v1);
                *(__half2*)(cp + (size_t)(r0+8)*Nn + c0) = __floats2half2_rn(v2, v3);
            } else {
                float* cp = (float*)Cout;
                *(float2*)(cp + (size_t)r0*Nn + c0)     = make_float2(v0, v1);
                *(float2*)(cp + (size_t)(r0+8)*Nn + c0) = make_float2(v2, v3);
            }
        }
    }
}

// ---------------- surrogate matrix r = d2/den via mini-GEMM ----------------
__global__ __launch_bounds__(256)
void rmat_kernel(const float* __restrict__ pos) {
    __shared__ float Pa[PDIM][RB];
    __shared__ float Pb[PDIM][RB];
    __shared__ float spa[RB], spb[RB], sca[RB], scb[RB];
    int b  = blockIdx.z;
    int bi = blockIdx.y*RB, bj = blockIdx.x*RB;
    int tid = threadIdx.x;
    const float* pbase = pos + (size_t)b*NTOK*PDIM;
    int r = tid & 127, dd = (tid >> 7) * 8;
    {
        const float* pr = pbase + (size_t)(bi + r)*PDIM + dd;
        float4 u0 = *(const float4*)pr, u1 = *(const float4*)(pr + 4);
        Pa[dd+0][r]=u0.x; Pa[dd+1][r]=u0.y; Pa[dd+2][r]=u0.z; Pa[dd+3][r]=u0.w;
        Pa[dd+4][r]=u1.x; Pa[dd+5][r]=u1.y; Pa[dd+6][r]=u1.z; Pa[dd+7][r]=u1.w;
        const float* qr = pbase + (size_t)(bj + r)*PDIM + dd;
        float4 w0 = *(const float4*)qr, w1 = *(const float4*)(qr + 4);
        Pb[dd+0][r]=w0.x; Pb[dd+1][r]=w0.y; Pb[dd+2][r]=w0.z; Pb[dd+3][r]=w0.w;
        Pb[dd+4][r]=w1.x; Pb[dd+5][r]=w1.y; Pb[dd+6][r]=w1.z; Pb[dd+7][r]=w1.w;
    }
    if (tid < RB) { spa[tid] = g_pnsq[b*NTOK+bi+tid]; sca[tid] = g_cx[b*NTOK+bi+tid]; }
    else          { int u = tid-RB; spb[u] = g_pnsq[b*NTOK+bj+u]; scb[u] = g_cx[b*NTOK+bj+u]; }
    __syncthreads();

    int ty = tid >> 4, tx = tid & 15;
    float acc[8][8];
    #pragma unroll
    for (int i = 0; i < 8; i++)
        #pragma unroll
        for (int j = 0; j < 8; j++) acc[i][j] = 0.f;

    #pragma unroll
    for (int d = 0; d < PDIM; d++) {
        float4 a0 = *(const float4*)&Pa[d][ty*8];
        float4 a1 = *(const float4*)&Pa[d][ty*8+4];
        float4 b0 = *(const float4*)&Pb[d][tx*8];
        float4 b1 = *(const float4*)&Pb[d][tx*8+4];
        float av[8] = {a0.x,a0.y,a0.z,a0.w,a1.x,a1.y,a1.z,a1.w};
        float bw[8] = {b0.x,b0.y,b0.z,b0.w,b1.x,b1.y,b1.z,b1.w};
        #pragma unroll
        for (int i = 0; i < 8; i++)
            #pragma unroll
            for (int j = 0; j < 8; j++)
                acc[i][j] = fmaf(av[i], bw[j], acc[i][j]);
    }

    #pragma unroll
    for (int i = 0; i < 8; i++) {
        int gi = ty*8 + i;
        float pni = spa[gi], cxi = sca[gi];
        float outv[8];
        #pragma unroll
        for (int j = 0; j < 8; j++) {
            int gj = tx*8 + j;
            float d2  = pni + spb[gj] - 2.f*acc[i][j];
            float den = fmaxf(cxi*scb[gj], 1e-8f);
            outv[j] = d2/den;
        }
        float* op = g_rmat + ((size_t)b*NTOK + bi + gi)*NTOK + bj + tx*8;
        *(float4*)op     = make_float4(outv[0],outv[1],outv[2],outv[3]);
        *(float4*)(op+4) = make_float4(outv[4],outv[5],outv[6],outv[7]);
    }
}

// ---------------- register-resident top-K ----------------
__global__ __launch_bounds__(256)
void topk_kernel(const float* __restrict__ cptr) {
    __shared__ float sval[8][32];
    __shared__ int   sjdx[8][32];
    int row = blockIdx.x;
    int tid = threadIdx.x, lane = tid & 31, w = tid >> 5;
    const float* rrow = g_rmat + (size_t)row*NTOK;
    float rv[8];
    #pragma unroll
    for (int it = 0; it < 8; it++) rv[it] = rrow[it*256 + tid];

    #pragma unroll 1
    for (int k = 0; k < KNN; k++) {
        float bv = rv[0]; int bs = 0;
        #pragma unroll
        for (int i = 1; i < 8; i++) if (rv[i] < bv) { bv = rv[i]; bs = i; }
        int bj = bs*256 + tid;
        #pragma unroll
        for (int o = 16; o; o >>= 1) {
            float ov = __shfl_xor_sync(0xffffffffu, bv, o);
            int   oj = __shfl_xor_sync(0xffffffffu, bj, o);
            if (ov < bv || (ov == bv && oj < bj)) { bv = ov; bj = oj; }
        }
        if ((bj & 255) == tid) {
            int slot = bj >> 8;
            #pragma unroll
            for (int i = 0; i < 8; i++) if (i == slot) rv[i] = 3.4e38f;
        }
        if (lane == k) { sval[w][k] = bv; sjdx[w][k] = bj; }
    }
    __syncthreads();

    if (w == 0) {
        float mv[8]; int mj[8];
        #pragma unroll
        for (int i = 0; i < 8; i++) { mv[i] = sval[i][lane]; mj[i] = sjdx[i][lane]; }
        float c = *cptr;
        float isc = rsqrtf(c);
        #pragma unroll 1
        for (int k = 0; k < KNN; k++) {
            float bv = mv[0]; int bs = 0; int bjv = mj[0];
            #pragma unroll
            for (int i = 1; i < 8; i++)
                if (mv[i] < bv || (mv[i] == bv && mj[i] < bjv)) { bv = mv[i]; bs = i; bjv = mj[i]; }
            int bj = bjv;
            int bc = bs*32 + lane;
            #pragma unroll
            for (int o = 16; o; o >>= 1) {
                float ov = __shfl_xor_sync(0xffffffffu, bv, o);
                int   oj = __shfl_xor_sync(0xffffffffu, bj, o);
                int   oc = __shfl_xor_sync(0xffffffffu, bc, o);
                if (ov < bv || (ov == bv && oj < bj)) { bv = ov; bj = oj; bc = oc; }
            }
            if (lane == (bc & 31)) {
                int slot = bc >> 5;
                #pragma unroll
                for (int i = 0; i < 8; i++) if (i == slot) mv[i] = 3.4e38f;
            }
            if (lane == k) {
                g_tidx[row*KNN + k] = bj;
                float arg = fmaxf(fmaf(2.f*c, bv, 1.f), 1.f + 1e-7f);
                g_tdist[row*KNN + k] = acoshf(arg) * isc;
            }
        }
    }
}

// ---------------- kNN attention: K staged via smem (coalesced gather) ----------------
#define KPITCH 257

__global__ __launch_bounds__(256)
void attn_kernel(const float* __restrict__ ltau, const float* __restrict__ ascl) {
    __shared__ uint32_t sk[KNN*KPITCH];
    __shared__ int   sidx[KNN];
    __shared__ float sdist[KNN];
    __shared__ float sw[NHEADS][KNN];
    int row = blockIdx.x;
    int b = row / NTOK;
    int t = threadIdx.x;
    int h = t >> 5, lane = t & 31;
    if (t < KNN) { sidx[t] = g_tidx[row*KNN + t]; sdist[t] = g_tdist[row*KNN + t]; }
    __syncthreads();

    #pragma unroll
    for (int rr = 0; rr < 4; rr++) {
        int j = h*4 + rr;
        const uint32_t* src = (const uint32_t*)(g_qkvh + (size_t)(b*NTOK + sidx[j])*QKVN + DIM);
        uint32_t* dst = &sk[j*KPITCH];
        #pragma unroll
        for (int it = 0; it < 8; it++)
            dst[it*32 + lane] = src[it*32 + lane];
    }
    __syncthreads();

    float inv_tau = 1.0f / fmaxf(__expf(ltau[0]), 1e-8f);
    float as = ascl[0];

    const __half* qrow = g_qkvh + (size_t)row*QKVN + h*HDIM;
    const uint32_t* krow = &sk[lane*KPITCH + h*32];
    float dot = 0.f;
    #pragma unroll
    for (int d8 = 0; d8 < 8; d8++) {
        float4 qb = *(const float4*)(qrow + d8*8);
        const __half2* q2 = (const __half2*)&qb;
        #pragma unroll
        for (int p = 0; p < 4; p++) {
            uint32_t kw = krow[d8*4 + p];
            float2 ka = __half22float2(*(const __half2*)&kw);
            float2 qa = __half22float2(q2[p]);
            dot = fmaf(qa.x, ka.x, dot);
            dot = fmaf(qa.y, ka.y, dot);
        }
    }
    float sc = as * fast_tanh(dot*0.125f - sdist[lane]*inv_tau);
    float mx = sc;
    #pragma unroll
    for (int o = 16; o; o >>= 1) mx = fmaxf(mx, __shfl_xor_sync(0xffffffffu, mx, o));
    float e = __expf(sc - mx);
    float sum = e;
    #pragma unroll
    for (int o = 16; o; o >>= 1) sum += __shfl_xor_sync(0xffffffffu, sum, o);
    sw[h][lane] = e / sum;
    __syncwarp();

    float o0 = 0.f, o1 = 0.f;
    #pragma unroll 8
    for (int j = 0; j < KNN; j++) {
        const __half* vrow = g_qkvh + (size_t)(b*NTOK + sidx[j])*QKVN + 2*DIM + h*HDIM;
        float2 vv = __half22float2(*(const __half2*)(vrow + lane*2));
        float wj = sw[h][j];
        o0 = fmaf(wj, vv.x, o0);
        o1 = fmaf(wj, vv.y, o1);
    }
    *(__half2*)(g_attnh + (size_t)row*DIM + h*HDIM + lane*2) = __floats2half2_rn(o0, o1);
}

// ---------------- launch ----------------
extern "C" void kernel_launch(void* const* d_in, const int* in_sizes, int n_in,
                              void* d_out, int out_size) {
    const float* x    = (const float*)d_in[0];
    const float* pos  = (const float*)d_in[1];
    const float* c    = (const float*)d_in[2];
    const float* Wq   = (const float*)d_in[3];
    const float* bq   = (const float*)d_in[4];
    const float* Wk   = (const float*)d_in[5];
    const float* bk   = (const float*)d_in[6];
    const float* Wv   = (const float*)d_in[7];
    const float* bv   = (const float*)d_in[8];
    const float* Wo   = (const float*)d_in[9];
    const float* bo   = (const float*)d_in[10];
    const float* W1   = (const float*)d_in[11];
    const float* b1   = (const float*)d_in[12];
    const float* W2   = (const float*)d_in[13];
    const float* b2   = (const float*)d_in[14];
    const float* ln1s = (const float*)d_in[15];
    const float* ln1b = (const float*)d_in[16];
    const float* ln2s = (const float*)d_in[17];
    const float* ln2b = (const float*)d_in[18];
    const float* ltau = (const float*)d_in[19];
    const float* ascl = (const float*)d_in[20];
    float* out = (float*)d_out;

    float *x1, *bqkv;
    __half *qkvh, *xnh, *ath, *x2h, *hih, *WqkvT, *WoT, *W1T, *W2T;
    cudaGetSymbolAddress((void**)&qkvh, g_qkvh);
    cudaGetSymbolAddress((void**)&x1,   g_x1);
    cudaGetSymbolAddress((void**)&bqkv, g_bqkv);
    cudaGetSymbolAddress((void**)&xnh,  g_xnormh);
    cudaGetSymbolAddress((void**)&ath,  g_attnh);
    cudaGetSymbolAddress((void**)&x2h,  g_x2nh);
    cudaGetSymbolAddress((void**)&hih,  g_hidh);
    cudaGetSymbolAddress((void**)&WqkvT, g_WqkvT);
    cudaGetSymbolAddress((void**)&WoT,  g_WoT);
    cudaGetSymbolAddress((void**)&W1T,  g_W1T);
    cudaGetSymbolAddress((void**)&W2T,  g_W2T);

    const int smem128 = NSTAGE * (128 + TN) * SPITCH * 2;   // 61,440 B
    const int smem64  = NSTAGE * (64  + TN) * SPITCH * 2;   // 46,080 B
    cudaFuncSetAttribute(hgemm_mma<3,128>, cudaFuncAttributeMaxDynamicSharedMemorySize, smem128);
    cudaFuncSetAttribute(hgemm_mma<2,128>, cudaFuncAttributeMaxDynamicSharedMemorySize, smem128);
    cudaFuncSetAttribute(hgemm_mma<1,64>,  cudaFuncAttributeMaxDynamicSharedMemorySize, smem64);

    dim3 gqkv(QKVN/TN, TOK/128);   // (12, 32)
    dim3 g512(DIM/TN,  TOK/64);    // (4, 64) for TM=64
    dim3 gh  (HID/TN,  TOK/128);   // (16, 32)

    prep_kernel<<<3089, 256>>>(Wq, Wk, Wv, Wo, W1, W2, bq, bk, bv, pos, c);
    ln_kernel<<<TOK, 256>>>(x, ln1s, ln1b, xnh);
    hgemm_mma<3,128><<<gqkv, 256, smem128>>>(xnh, WqkvT, bqkv, nullptr, qkvh, QKVN, DIM);
    rmat_kernel<<<dim3(NTOK/RB, NTOK/RB, BATCH), 256>>>(pos);
    topk_kernel<<<TOK, 256>>>(c);
    attn_kernel<<<TOK, 256>>>(ltau, ascl);
    hgemm_mma<1,64><<<g512, 256, smem64>>>(ath, WoT, bo, x, x1, DIM, DIM);
    ln_kernel<<<TOK, 256>>>(x1, ln2s, ln2b, x2h);
    hgemm_mma<2,128><<<gh, 256, smem128>>>(x2h, W1T, b1, nullptr, hih, HID, DIM);
    hgemm_mma<1,64><<<g512, 256, smem64>>>(hih, W2T, b2, x1, out, DIM, HID);
}